// round 5
// baseline (speedup 1.0000x reference)
#include <cuda_runtime.h>
#include <math.h>

// Problem constants: x is (8, 3, 1280, 1280) fp32, NCHW.
#define NPLANES 24            // 8 * 3 depthwise planes
#define H0 1280
#define W0 1280

// Pyramid scratch (device globals: allocation-free at launch time)
__device__ float g_pyr1[NPLANES * 640 * 640];
__device__ float g_pyr2[NPLANES * 320 * 320];
__device__ float g_pyr3[NPLANES * 160 * 160];
__device__ float g_pyr4[NPLANES * 80 * 80];
__device__ float g_pyr5[NPLANES * 40 * 40];
__device__ float g_pyr6[NPLANES * 20 * 20];
__device__ float g_pyr7[NPLANES * 10 * 10];
__device__ float g_pyr8[NPLANES * 5 * 5];

// Filter results at 320x320 (last TWO 2x upsamples fused into composite)
__device__ float g_f30 [NPLANES * 320 * 320];
__device__ float g_f150[NPLANES * 320 * 320];
__device__ float g_f300[NPLANES * 320 * 320];

// Ping-pong temps for upsample chains (max intermediate 160x160)
__device__ float g_tmpA[NPLANES * 160 * 160];
__device__ float g_tmpB[NPLANES * 160 * 160];

__device__ __forceinline__ int refl101(int i, int n) {
    // reflect-101 (cv2 BORDER_REFLECT_101 / jnp.pad mode='reflect'), pad <= n-1
    if (i < 0) i = -i;
    if (i >= n) i = 2 * n - 2 - i;
    return i;
}

// ---------------------------------------------------------------------------
// pyrDown: 5x5 binomial, reflect-101 pad 2, stride 2.  src HxW -> dst H/2 x W/2
// ---------------------------------------------------------------------------
__global__ void pyrdown_kernel(const float* __restrict__ src,
                               float* __restrict__ dst, int H, int W) {
    const int Ho = H >> 1, Wo = W >> 1;
    const int total = NPLANES * Ho * Wo;
    int idx = blockIdx.x * blockDim.x + threadIdx.x;
    if (idx >= total) return;
    int wo = idx % Wo;
    int t  = idx / Wo;
    int ho = t % Ho;
    int p  = t / Ho;
    const float* s = src + (size_t)p * H * W;
    const float k1[5] = {0.0625f, 0.25f, 0.375f, 0.25f, 0.0625f};
    float acc = 0.f;
#pragma unroll
    for (int dy = 0; dy < 5; dy++) {
        int y = refl101(2 * ho + dy - 2, H);
        const float* row = s + (size_t)y * W;
        float r = 0.f;
#pragma unroll
        for (int dx = 0; dx < 5; dx++) {
            r += k1[dx] * row[refl101(2 * wo + dx - 2, W)];
        }
        acc += k1[dy] * r;
    }
    dst[idx] = acc;
}

// ---------------------------------------------------------------------------
// Gaussian blur, ksize 7 or 9, sigma = 0.3*((k-1)*0.5-1)+0.8, reflect-101 pad.
// Tiny grids only (<=40x40), brute force is fine.
// ---------------------------------------------------------------------------
__global__ void blur_kernel(const float* __restrict__ src,
                            float* __restrict__ dst, int H, int W, int ks) {
    const int total = NPLANES * H * W;
    int idx = blockIdx.x * blockDim.x + threadIdx.x;
    if (idx >= total) return;

    float g[9];
    float sg = 0.3f * ((ks - 1) * 0.5f - 1.f) + 0.8f;
    float inv2s2 = 1.f / (2.f * sg * sg);
    float sum = 0.f;
    for (int i = 0; i < ks; i++) {
        float d = (float)i - (ks - 1) * 0.5f;
        g[i] = expf(-d * d * inv2s2);
        sum += g[i];
    }
    float inv = 1.f / sum;
    for (int i = 0; i < ks; i++) g[i] *= inv;

    int w = idx % W;
    int t = idx / W;
    int h = t % H;
    int p = t / H;
    const float* sp = src + (size_t)p * H * W;
    int P = ks / 2;
    float acc = 0.f;
    for (int dy = 0; dy < ks; dy++) {
        int y = refl101(h + dy - P, H);
        const float* row = sp + (size_t)y * W;
        float r = 0.f;
        for (int dx = 0; dx < ks; dx++)
            r += g[dx] * row[refl101(w + dx - P, W)];
        acc += g[dy] * r;
    }
    dst[idx] = acc;
}

// ---------------------------------------------------------------------------
// 2x bilinear upsample, half-pixel centers, clamp-to-edge (== jax.image.resize
// bilinear for exact 2x). src HxW -> dst 2H x 2W.
// ---------------------------------------------------------------------------
__global__ void up2_kernel(const float* __restrict__ src,
                           float* __restrict__ dst, int H, int W) {
    const int Ho = 2 * H, Wo = 2 * W;
    const int total = NPLANES * Ho * Wo;
    int idx = blockIdx.x * blockDim.x + threadIdx.x;
    if (idx >= total) return;
    int wo = idx % Wo;
    int t  = idx / Wo;
    int ho = t % Ho;
    int p  = t / Ho;

    int iy = (ho >> 1) + (ho & 1) - 1;   // floor(0.5*ho - 0.25)
    float fy = (ho & 1) ? 0.25f : 0.75f;
    int y0 = max(iy, 0), y1 = min(iy + 1, H - 1);
    int ix = (wo >> 1) + (wo & 1) - 1;
    float fx = (wo & 1) ? 0.25f : 0.75f;
    int x0 = max(ix, 0), x1 = min(ix + 1, W - 1);

    const float* s = src + (size_t)p * H * W;
    float v00 = s[(size_t)y0 * W + x0], v01 = s[(size_t)y0 * W + x1];
    float v10 = s[(size_t)y1 * W + x0], v11 = s[(size_t)y1 * W + x1];
    float top = v00 + fx * (v01 - v00);
    float bot = v10 + fx * (v11 - v10);
    dst[idx] = top + fy * (bot - top);
}

// ---------------------------------------------------------------------------
// Iterated 2x bilinear sample: evaluate, at output pixel (h, w) on the 1280
// grid, the value of up2(up2(f)) where f lives on the 320 grid. Each level
// uses half-pixel centers with clamp-to-edge, identical arithmetic to
// up2_kernel applied twice.
// ---------------------------------------------------------------------------
struct Up2Coord {
    int y0, y1;      // source rows (clamped)
    float fy;        // lerp weight toward y1
};

__device__ __forceinline__ Up2Coord up2_coord(int ho, int N) {
    Up2Coord c;
    int iy = (ho >> 1) + (ho & 1) - 1;
    c.fy = (ho & 1) ? 0.25f : 0.75f;
    c.y0 = max(iy, 0);
    c.y1 = min(iy + 1, N - 1);
    return c;
}

// Sample one filter plane (320x320) through two 2x bilinear upsamples at
// output position given by precomputed coords. cy/cx are the 1280-level
// coords; for each of the 4 needed 640-level samples we compute the
// 320-level bilerp directly.
__device__ __forceinline__ float sample2up(const float* __restrict__ f,
                                           const Up2Coord& cy1280, const Up2Coord& cx1280) {
    // 640-level sample positions needed: (cy1280.y0|y1, cx1280.x0|x1)
    // For each, its own 320-level coords:
    Up2Coord ry0 = up2_coord(cy1280.y0, 320);
    Up2Coord ry1 = up2_coord(cy1280.y1, 320);
    Up2Coord rx0 = up2_coord(cx1280.y0, 320);
    Up2Coord rx1 = up2_coord(cx1280.y1, 320);

    // Gather the (up to) 3x3 320-level footprint rows
    // Evaluate the four 640-level samples:
    auto bl320 = [&](const Up2Coord& ry, const Up2Coord& rx) -> float {
        float v00 = f[(size_t)ry.y0 * 320 + rx.y0];
        float v01 = f[(size_t)ry.y0 * 320 + rx.y1];
        float v10 = f[(size_t)ry.y1 * 320 + rx.y0];
        float v11 = f[(size_t)ry.y1 * 320 + rx.y1];
        float tp = v00 + rx.fy * (v01 - v00);
        float bt = v10 + rx.fy * (v11 - v10);
        return tp + ry.fy * (bt - tp);
    };
    float u00 = bl320(ry0, rx0);
    float u01 = bl320(ry0, rx1);
    float u10 = bl320(ry1, rx0);
    float u11 = bl320(ry1, rx1);

    float tp = u00 + cx1280.fy * (u01 - u00);
    float bt = u10 + cx1280.fy * (u11 - u10);
    return tp + cy1280.fy * (bt - tp);
}

// ---------------------------------------------------------------------------
// Composite: fused double 2x upsample (320->1280) of the three filters +
// retinex + color restoration + gain/offset/clip.
// filt(img) = 255 * filt(x) + 1 (all filters affine, weights sum to 1).
// retinex = log10(img+eps) - log10( prod_s (f_s+eps) ) / 3
// ---------------------------------------------------------------------------
__global__ void composite_kernel(const float* __restrict__ x,
                                 const float* __restrict__ f30,
                                 const float* __restrict__ f150,
                                 const float* __restrict__ f300,
                                 float* __restrict__ out) {
    const int total = 8 * H0 * W0;
    int idx = blockIdx.x * blockDim.x + threadIdx.x;
    if (idx >= total) return;
    int w = idx % W0;
    int t = idx / W0;
    int h = t % H0;
    int n = t / H0;

    Up2Coord cy = up2_coord(h, 640);   // 1280 -> 640 level coords
    Up2Coord cx = up2_coord(w, 640);

    const size_t pix1280  = (size_t)h * W0 + w;
    const size_t base1280 = (size_t)n * 3 * H0 * W0 + pix1280;
    const size_t base320  = (size_t)n * 3 * 320 * 320;

    const float LOG10_2 = 0.30102999566398f;
    const float EPS = 1e-6f;

    float img[3], lprod[3];
    float imgsum = 0.f;

#pragma unroll
    for (int c = 0; c < 3; c++) {
        float xv = x[base1280 + (size_t)c * H0 * W0];
        float im = xv * 255.f + 1.f;
        img[c] = im;
        imgsum += im;

        const float* pf30  = f30  + base320 + (size_t)c * 320 * 320;
        const float* pf150 = f150 + base320 + (size_t)c * 320 * 320;
        const float* pf300 = f300 + base320 + (size_t)c * 320 * 320;

        float a  = 255.f * sample2up(pf30,  cy, cx) + 1.f;
        float b  = 255.f * sample2up(pf150, cy, cx) + 1.f;
        float cc = 255.f * sample2up(pf300, cy, cx) + 1.f;
        lprod[c] = __log2f((a + EPS) * (b + EPS) * (cc + EPS));
    }

    float inv_sum = 2.f / (imgsum + EPS);
#pragma unroll
    for (int c = 0; c < 3; c++) {
        float im = img[c];
        float l_img = __log2f(im + EPS);
        float retinex = (l_img - lprod[c] * (1.f / 3.f)) * LOG10_2;
        float cr = __log2f(im * inv_sum + 1.f) * LOG10_2;
        float e = retinex * cr * 2700.f + 128.f;   // COLOR_GAIN*GAIN = 2700
        e = fminf(fmaxf(e, 0.f), 255.f);
        out[base1280 + (size_t)c * H0 * W0] = e * (1.f / 255.f);
    }
}

// ---------------------------------------------------------------------------
// Launch
// ---------------------------------------------------------------------------
static inline int nblk(long long n, int t) { return (int)((n + t - 1) / t); }

extern "C" void kernel_launch(void* const* d_in, const int* in_sizes, int n_in,
                              void* d_out, int out_size) {
    const float* x = (const float*)d_in[0];
    float* out = (float*)d_out;

    float *p1, *p2, *p3, *p4, *p5, *p6, *p7, *p8;
    float *f30, *f150, *f300, *tA, *tB;
    cudaGetSymbolAddress((void**)&p1, g_pyr1);
    cudaGetSymbolAddress((void**)&p2, g_pyr2);
    cudaGetSymbolAddress((void**)&p3, g_pyr3);
    cudaGetSymbolAddress((void**)&p4, g_pyr4);
    cudaGetSymbolAddress((void**)&p5, g_pyr5);
    cudaGetSymbolAddress((void**)&p6, g_pyr6);
    cudaGetSymbolAddress((void**)&p7, g_pyr7);
    cudaGetSymbolAddress((void**)&p8, g_pyr8);
    cudaGetSymbolAddress((void**)&f30, g_f30);
    cudaGetSymbolAddress((void**)&f150, g_f150);
    cudaGetSymbolAddress((void**)&f300, g_f300);
    cudaGetSymbolAddress((void**)&tA, g_tmpA);
    cudaGetSymbolAddress((void**)&tB, g_tmpB);

    const int T = 256;
    // Shared pyramid of x
    pyrdown_kernel<<<nblk((long long)NPLANES * 640 * 640, T), T>>>(x,  p1, 1280, 1280);
    pyrdown_kernel<<<nblk((long long)NPLANES * 320 * 320, T), T>>>(p1, p2, 640, 640);
    pyrdown_kernel<<<nblk((long long)NPLANES * 160 * 160, T), T>>>(p2, p3, 320, 320);
    pyrdown_kernel<<<nblk((long long)NPLANES * 80 * 80,   T), T>>>(p3, p4, 160, 160);
    pyrdown_kernel<<<nblk((long long)NPLANES * 40 * 40,   T), T>>>(p4, p5, 80, 80);
    pyrdown_kernel<<<nblk((long long)NPLANES * 20 * 20,   T), T>>>(p5, p6, 40, 40);
    pyrdown_kernel<<<nblk((long long)NPLANES * 10 * 10,   T), T>>>(p6, p7, 20, 20);
    pyrdown_kernel<<<nblk((long long)NPLANES * 5 * 5,     T), T>>>(p7, p8, 10, 10);

    // sigma=30: blur7 @ 40, then up to 320 (two more ups fused into composite)
    blur_kernel<<<nblk((long long)NPLANES * 40 * 40, T), T>>>(p5, tA, 40, 40, 7);
    up2_kernel<<<nblk((long long)NPLANES * 80 * 80,   T), T>>>(tA, tB, 40, 40);
    up2_kernel<<<nblk((long long)NPLANES * 160 * 160, T), T>>>(tB, tA, 80, 80);
    up2_kernel<<<nblk((long long)NPLANES * 320 * 320, T), T>>>(tA, f30, 160, 160);

    // sigma=150: blur9 @ 10, then up to 320
    blur_kernel<<<nblk((long long)NPLANES * 10 * 10, T), T>>>(p7, tA, 10, 10, 9);
    up2_kernel<<<nblk((long long)NPLANES * 20 * 20,   T), T>>>(tA, tB, 10, 10);
    up2_kernel<<<nblk((long long)NPLANES * 40 * 40,   T), T>>>(tB, tA, 20, 20);
    up2_kernel<<<nblk((long long)NPLANES * 80 * 80,   T), T>>>(tA, tB, 40, 40);
    up2_kernel<<<nblk((long long)NPLANES * 160 * 160, T), T>>>(tB, tA, 80, 80);
    up2_kernel<<<nblk((long long)NPLANES * 320 * 320, T), T>>>(tA, f150, 160, 160);

    // sigma=300: blur9 @ 5, then up to 320
    blur_kernel<<<nblk((long long)NPLANES * 5 * 5, T), T>>>(p8, tA, 5, 5, 9);
    up2_kernel<<<nblk((long long)NPLANES * 10 * 10,   T), T>>>(tA, tB, 5, 5);
    up2_kernel<<<nblk((long long)NPLANES * 20 * 20,   T), T>>>(tB, tA, 10, 10);
    up2_kernel<<<nblk((long long)NPLANES * 40 * 40,   T), T>>>(tA, tB, 20, 20);
    up2_kernel<<<nblk((long long)NPLANES * 80 * 80,   T), T>>>(tB, tA, 40, 40);
    up2_kernel<<<nblk((long long)NPLANES * 160 * 160, T), T>>>(tA, tB, 80, 80);
    up2_kernel<<<nblk((long long)NPLANES * 320 * 320, T), T>>>(tB, f300, 160, 160);

    // Final fused composite at 1280x1280 (320->640->1280 upsample inline)
    composite_kernel<<<nblk((long long)8 * H0 * W0, T), T>>>(x, f30, f150, f300, out);
}

// round 6
// speedup vs baseline: 1.8393x; 1.8393x over previous
#include <cuda_runtime.h>
#include <math.h>

// Problem constants: x is (8, 3, 1280, 1280) fp32, NCHW.
#define NPLANES 24            // 8 * 3 depthwise planes
#define H0 1280
#define W0 1280

// ---------------------------------------------------------------------------
// Scratch (device globals: allocation-free)
// ---------------------------------------------------------------------------
__device__ float g_pyr1[NPLANES * 640 * 640];
__device__ float g_pyr2[NPLANES * 320 * 320];
__device__ float g_pyr3[NPLANES * 160 * 160];
__device__ float g_pyr4[NPLANES * 80 * 80];
__device__ float g_pyr5[NPLANES * 40 * 40];
__device__ float g_pyr6[NPLANES * 20 * 20];
__device__ float g_pyr7[NPLANES * 10 * 10];
__device__ float g_pyr8[NPLANES * 5 * 5];

// chain ping-pong (per sigma, per plane, levels <= 80)
__device__ float g_chA[3 * NPLANES * 80 * 80];
__device__ float g_chB[3 * NPLANES * 80 * 80];
// chain outputs at 160 level (per sigma)
__device__ float g_t160[3 * NPLANES * 160 * 160];
// packed filters at 320 level: {f30, f150, f300, pad}
__device__ float4 g_pack[NPLANES * 320 * 320];

__device__ __forceinline__ int refl101(int i, int n) {
    if (i < 0) i = -i;
    if (i >= n) i = 2 * n - 2 - i;
    return i;
}

// ---------------------------------------------------------------------------
// pyrDown, 4 horizontal outputs per thread, interior fast path.
// 5x5 binomial, reflect-101 pad 2, stride 2.
// ---------------------------------------------------------------------------
__global__ void pyrdown4_kernel(const float* __restrict__ src,
                                float* __restrict__ dst, int H, int W) {
    const int Ho = H >> 1, Wo = W >> 1, Wq = Wo >> 2;
    const int total = NPLANES * Ho * Wq;
    int idx = blockIdx.x * blockDim.x + threadIdx.x;
    if (idx >= total) return;
    int wq = idx % Wq;
    int t  = idx / Wq;
    int ho = t % Ho;
    int p  = t / Ho;
    int wo0 = wq << 2;

    const float* s = src + (size_t)p * H * W;
    const float kk[5] = {0.0625f, 0.25f, 0.375f, 0.25f, 0.0625f};
    float acc[4] = {0.f, 0.f, 0.f, 0.f};

    bool interior = (ho >= 1) && (2 * ho + 2 <= H - 1) &&
                    (wo0 >= 1) && (2 * wo0 + 8 <= W - 1);
    if (interior) {
        const float* r = s + (size_t)(2 * ho - 2) * W + (2 * wo0 - 2);
#pragma unroll
        for (int dy = 0; dy < 5; dy++, r += W) {
            float v[11];
#pragma unroll
            for (int q = 0; q < 11; q++) v[q] = __ldg(r + q);
            float ky = kk[dy];
#pragma unroll
            for (int o = 0; o < 4; o++) {
                float hs = 0.0625f * (v[2 * o] + v[2 * o + 4])
                         + 0.25f   * (v[2 * o + 1] + v[2 * o + 3])
                         + 0.375f  *  v[2 * o + 2];
                acc[o] += ky * hs;
            }
        }
    } else {
#pragma unroll
        for (int o = 0; o < 4; o++) {
            int wo = wo0 + o;
            float a = 0.f;
#pragma unroll
            for (int dy = 0; dy < 5; dy++) {
                int y = refl101(2 * ho + dy - 2, H);
                const float* row = s + (size_t)y * W;
                float r2 = 0.f;
#pragma unroll
                for (int dx = 0; dx < 5; dx++)
                    r2 += kk[dx] * row[refl101(2 * wo + dx - 2, W)];
                a += kk[dy] * r2;
            }
            acc[o] = a;
        }
    }
    float4* d = (float4*)(dst + (size_t)p * Ho * Wo + (size_t)ho * Wo + wo0);
    *d = make_float4(acc[0], acc[1], acc[2], acc[3]);
}

// ---------------------------------------------------------------------------
// Per-plane device helpers (used by fused small-level kernels)
// ---------------------------------------------------------------------------
__device__ void pyrdown_plane(const float* __restrict__ s, float* __restrict__ d,
                              int N, int tid, int nt) {
    const int No = N >> 1;
    const int total = No * No;
    const float kk[5] = {0.0625f, 0.25f, 0.375f, 0.25f, 0.0625f};
    for (int idx = tid; idx < total; idx += nt) {
        int wo = idx % No, ho = idx / No;
        float acc = 0.f;
#pragma unroll
        for (int dy = 0; dy < 5; dy++) {
            int y = refl101(2 * ho + dy - 2, N);
            const float* row = s + y * N;
            float r = 0.f;
#pragma unroll
            for (int dx = 0; dx < 5; dx++)
                r += kk[dx] * row[refl101(2 * wo + dx - 2, N)];
            acc += kk[dy] * r;
        }
        d[idx] = acc;
    }
}

__device__ void up2_plane(const float* __restrict__ s, float* __restrict__ d,
                          int N, int tid, int nt) {
    const int No = 2 * N;
    const int total = No * No;
    for (int idx = tid; idx < total; idx += nt) {
        int wo = idx % No, ho = idx / No;
        int iy = (ho >> 1) + (ho & 1) - 1;
        float fy = (ho & 1) ? 0.25f : 0.75f;
        int y0 = max(iy, 0), y1 = min(iy + 1, N - 1);
        int ix = (wo >> 1) + (wo & 1) - 1;
        float fx = (wo & 1) ? 0.25f : 0.75f;
        int x0 = max(ix, 0), x1 = min(ix + 1, N - 1);
        float v00 = s[y0 * N + x0], v01 = s[y0 * N + x1];
        float v10 = s[y1 * N + x0], v11 = s[y1 * N + x1];
        float tp = v00 + fx * (v01 - v00);
        float bt = v10 + fx * (v11 - v10);
        d[idx] = tp + fy * (bt - tp);
    }
}

__device__ void blur_plane(const float* __restrict__ s, float* __restrict__ d,
                           int N, int ks, int tid, int nt) {
    float g[9];
    float sg = 0.3f * ((ks - 1) * 0.5f - 1.f) + 0.8f;
    float inv2s2 = 1.f / (2.f * sg * sg);
    float sum = 0.f;
    for (int i = 0; i < ks; i++) {
        float dd = (float)i - (ks - 1) * 0.5f;
        g[i] = expf(-dd * dd * inv2s2);
        sum += g[i];
    }
    float inv = 1.f / sum;
    for (int i = 0; i < ks; i++) g[i] *= inv;

    int P = ks / 2;
    const int total = N * N;
    for (int idx = tid; idx < total; idx += nt) {
        int w = idx % N, h = idx / N;
        float acc = 0.f;
        for (int dy = 0; dy < ks; dy++) {
            int y = refl101(h + dy - P, N);
            const float* row = s + y * N;
            float r = 0.f;
            for (int dx = 0; dx < ks; dx++)
                r += g[dx] * row[refl101(w + dx - P, N)];
            acc += g[dy] * r;
        }
        d[idx] = acc;
    }
}

// ---------------------------------------------------------------------------
// Fused small pyramid: 80 -> 40 -> 20 -> 10 -> 5, one block per plane.
// ---------------------------------------------------------------------------
__global__ void smallpyr_kernel(const float* __restrict__ p4,
                                float* __restrict__ p5, float* __restrict__ p6,
                                float* __restrict__ p7, float* __restrict__ p8) {
    int p = blockIdx.x;
    int tid = threadIdx.x, nt = blockDim.x;
    pyrdown_plane(p4 + (size_t)p * 6400, p5 + (size_t)p * 1600, 80, tid, nt);
    __syncthreads();
    pyrdown_plane(p5 + (size_t)p * 1600, p6 + (size_t)p * 400, 40, tid, nt);
    __syncthreads();
    pyrdown_plane(p6 + (size_t)p * 400, p7 + (size_t)p * 100, 20, tid, nt);
    __syncthreads();
    pyrdown_plane(p7 + (size_t)p * 100, p8 + (size_t)p * 25, 10, tid, nt);
}

// ---------------------------------------------------------------------------
// Fused chains: block = (plane, sigma). blur + up2 chain to 160 level.
//  s=0 (sig30):  blur7 @40  -> up 80 -> 160
//  s=1 (sig150): blur9 @10  -> up 20 -> 40 -> 80 -> 160
//  s=2 (sig300): blur9 @5   -> up 10 -> 20 -> 40 -> 80 -> 160
// ---------------------------------------------------------------------------
__global__ void chains_kernel(const float* __restrict__ p5,
                              const float* __restrict__ p7,
                              const float* __restrict__ p8,
                              float* __restrict__ chA, float* __restrict__ chB,
                              float* __restrict__ t160) {
    int p = blockIdx.x;
    int sg = blockIdx.y;
    int tid = threadIdx.x, nt = blockDim.x;
    size_t so = (size_t)sg * NPLANES + p;
    float* A = chA + so * 6400;
    float* B = chB + so * 6400;
    float* T = t160 + so * 25600;

    if (sg == 0) {
        blur_plane(p5 + (size_t)p * 1600, A, 40, 7, tid, nt); __syncthreads();
        up2_plane(A, B, 40, tid, nt); __syncthreads();
        up2_plane(B, T, 80, tid, nt);
    } else if (sg == 1) {
        blur_plane(p7 + (size_t)p * 100, A, 10, 9, tid, nt); __syncthreads();
        up2_plane(A, B, 10, tid, nt); __syncthreads();
        up2_plane(B, A, 20, tid, nt); __syncthreads();
        up2_plane(A, B, 40, tid, nt); __syncthreads();
        up2_plane(B, T, 80, tid, nt);
    } else {
        blur_plane(p8 + (size_t)p * 25, A, 5, 9, tid, nt); __syncthreads();
        up2_plane(A, B, 5, tid, nt); __syncthreads();
        up2_plane(B, A, 10, tid, nt); __syncthreads();
        up2_plane(A, B, 20, tid, nt); __syncthreads();
        up2_plane(B, A, 40, tid, nt); __syncthreads();
        up2_plane(A, T, 80, tid, nt);
    }
}

// ---------------------------------------------------------------------------
// Packed up2 160 -> 320 for all three filters -> float4 {f30, f150, f300, 0}
// ---------------------------------------------------------------------------
__global__ void pack_kernel(const float* __restrict__ t160,
                            float4* __restrict__ pack) {
    const int total = NPLANES * 320 * 320;
    int idx = blockIdx.x * blockDim.x + threadIdx.x;
    if (idx >= total) return;
    int xo = idx % 320;
    int t  = idx / 320;
    int yo = t % 320;
    int p  = t / 320;

    int iy = (yo >> 1) + (yo & 1) - 1;
    float fy = (yo & 1) ? 0.25f : 0.75f;
    int y0 = max(iy, 0), y1 = min(iy + 1, 159);
    int ix = (xo >> 1) + (xo & 1) - 1;
    float fx = (xo & 1) ? 0.25f : 0.75f;
    int x0 = max(ix, 0), x1 = min(ix + 1, 159);

    float v[3];
#pragma unroll
    for (int s = 0; s < 3; s++) {
        const float* f = t160 + ((size_t)s * NPLANES + p) * 25600;
        float v00 = f[y0 * 160 + x0], v01 = f[y0 * 160 + x1];
        float v10 = f[y1 * 160 + x0], v11 = f[y1 * 160 + x1];
        float tp = v00 + fx * (v01 - v00);
        float bt = v10 + fx * (v11 - v10);
        v[s] = tp + fy * (bt - tp);
    }
    pack[idx] = make_float4(v[0], v[1], v[2], 0.f);
}

// ---------------------------------------------------------------------------
// Composite quad: one thread = 2x2 output pixels, all 3 channels.
// Iterated bilinear 320 -> 640 -> 1280 evaluated from a shared 3x3 patch of
// the packed 320-level filters, then retinex + color restore + clip.
// ---------------------------------------------------------------------------
__device__ __forceinline__ float4 f4lerp(float4 a, float4 b, float f) {
    return make_float4(a.x + f * (b.x - a.x), a.y + f * (b.y - a.y),
                       a.z + f * (b.z - a.z), 0.f);
}

__global__ void __launch_bounds__(128)
composite_quad_kernel(const float* __restrict__ x,
                      const float4* __restrict__ pack,
                      float* __restrict__ out) {
    const int total = 8 * 640 * 640;
    int idx = blockIdx.x * blockDim.x + threadIdx.x;
    if (idx >= total) return;
    int j = idx % 640;          // 640-level cell col
    int t = idx / 640;
    int i = t % 640;            // 640-level cell row
    int n = t / 640;

    int m  = i >> 1;            // 320-level center row
    int mq = j >> 1;            // 320-level center col
    int pr[3] = {max(m - 1, 0), m, min(m + 1, 319)};
    int pc[3] = {max(mq - 1, 0), mq, min(mq + 1, 319)};

    // mapping of the three 640-rows {i-1, i, i+1} onto patch row pairs
    int rsel[3]; float rfy[3];
    if (i & 1) { rsel[0] = 0; rsel[1] = 1; rsel[2] = 1;
                 rfy[0] = 0.75f; rfy[1] = 0.25f; rfy[2] = 0.75f; }
    else       { rsel[0] = 0; rsel[1] = 0; rsel[2] = 1;
                 rfy[0] = 0.25f; rfy[1] = 0.75f; rfy[2] = 0.25f; }
    int csel[3]; float cfx[3];
    if (j & 1) { csel[0] = 0; csel[1] = 1; csel[2] = 1;
                 cfx[0] = 0.75f; cfx[1] = 0.25f; cfx[2] = 0.75f; }
    else       { csel[0] = 0; csel[1] = 0; csel[2] = 1;
                 cfx[0] = 0.25f; cfx[1] = 0.75f; cfx[2] = 0.25f; }

    const float EPS = 1e-6f;
    const float LOG10_2 = 0.30102999566398f;

    float lp[3][2][2];
    float img[3][2][2];

#pragma unroll
    for (int c = 0; c < 3; c++) {
        const float4* pp = pack + (size_t)(n * 3 + c) * 320 * 320;
        // 3x3 patch at 320 level (all 3 filters in float4 lanes)
        float4 P[3][3];
#pragma unroll
        for (int a = 0; a < 3; a++)
#pragma unroll
            for (int b = 0; b < 3; b++)
                P[a][b] = pp[(size_t)pr[a] * 320 + pc[b]];

        // row-lerped intermediates for the three 640-rows
        float4 tr[3][3];
#pragma unroll
        for (int rr = 0; rr < 3; rr++) {
            int s = rsel[rr]; float f = rfy[rr];
#pragma unroll
            for (int cc = 0; cc < 3; cc++)
                tr[rr][cc] = f4lerp(P[s][cc], P[s + 1][cc], f);
        }
        // 640-level samples u[3][3]
        float4 u[3][3];
#pragma unroll
        for (int rr = 0; rr < 3; rr++)
#pragma unroll
            for (int cc = 0; cc < 3; cc++) {
                int s = csel[cc];
                u[rr][cc] = f4lerp(tr[rr][s], tr[rr][s + 1], cfx[cc]);
            }

        // 4 output pixels: 1280-level bilerp over u
#pragma unroll
        for (int py = 0; py < 2; py++) {
            int rA = py ? 1 : 0, rB = py ? 2 : 1;
            float wy = py ? 0.25f : 0.75f;
#pragma unroll
            for (int px = 0; px < 2; px++) {
                int cA = px ? 1 : 0, cB = px ? 2 : 1;
                float wx = px ? 0.25f : 0.75f;
                float4 q0 = f4lerp(u[rA][cA], u[rA][cB], wx);
                float4 q1 = f4lerp(u[rB][cA], u[rB][cB], wx);
                float4 v  = f4lerp(q0, q1, wy);
                float a  = 255.f * v.x + 1.f;
                float b  = 255.f * v.y + 1.f;
                float cc = 255.f * v.z + 1.f;
                lp[c][py][px] = __log2f((a + EPS) * (b + EPS) * (cc + EPS));
            }
        }

        // image values (float2 across the two columns)
        const float* xp = x + (size_t)(n * 3 + c) * H0 * W0;
#pragma unroll
        for (int py = 0; py < 2; py++) {
            float2 xv = *(const float2*)(xp + (size_t)(2 * i + py) * W0 + 2 * j);
            img[c][py][0] = xv.x * 255.f + 1.f;
            img[c][py][1] = xv.y * 255.f + 1.f;
        }
    }

    float res[3][2][2];
#pragma unroll
    for (int py = 0; py < 2; py++)
#pragma unroll
        for (int px = 0; px < 2; px++) {
            float s = img[0][py][px] + img[1][py][px] + img[2][py][px];
            float inv_sum = 2.f / (s + EPS);
#pragma unroll
            for (int c = 0; c < 3; c++) {
                float im = img[c][py][px];
                float retinex = (__log2f(im + EPS) - lp[c][py][px] * (1.f / 3.f)) * LOG10_2;
                float cr = __log2f(im * inv_sum + 1.f) * LOG10_2;
                float e = retinex * cr * 2700.f + 128.f;   // COLOR_GAIN*GAIN
                e = fminf(fmaxf(e, 0.f), 255.f);
                res[c][py][px] = e * (1.f / 255.f);
            }
        }

#pragma unroll
    for (int c = 0; c < 3; c++) {
        float* op = out + (size_t)(n * 3 + c) * H0 * W0;
#pragma unroll
        for (int py = 0; py < 2; py++) {
            *(float2*)(op + (size_t)(2 * i + py) * W0 + 2 * j) =
                make_float2(res[c][py][0], res[c][py][1]);
        }
    }
}

// ---------------------------------------------------------------------------
// Launch
// ---------------------------------------------------------------------------
static inline int nblk(long long n, int t) { return (int)((n + t - 1) / t); }

extern "C" void kernel_launch(void* const* d_in, const int* in_sizes, int n_in,
                              void* d_out, int out_size) {
    const float* x = (const float*)d_in[0];
    float* out = (float*)d_out;

    float *p1, *p2, *p3, *p4, *p5, *p6, *p7, *p8;
    float *chA, *chB, *t160;
    float4* pack;
    cudaGetSymbolAddress((void**)&p1, g_pyr1);
    cudaGetSymbolAddress((void**)&p2, g_pyr2);
    cudaGetSymbolAddress((void**)&p3, g_pyr3);
    cudaGetSymbolAddress((void**)&p4, g_pyr4);
    cudaGetSymbolAddress((void**)&p5, g_pyr5);
    cudaGetSymbolAddress((void**)&p6, g_pyr6);
    cudaGetSymbolAddress((void**)&p7, g_pyr7);
    cudaGetSymbolAddress((void**)&p8, g_pyr8);
    cudaGetSymbolAddress((void**)&chA, g_chA);
    cudaGetSymbolAddress((void**)&chB, g_chB);
    cudaGetSymbolAddress((void**)&t160, g_t160);
    cudaGetSymbolAddress((void**)&pack, g_pack);

    const int T = 256;
    // Shared pyramid of x (4 wide levels, then fused small levels)
    pyrdown4_kernel<<<nblk((long long)NPLANES * 640 * 160, T), T>>>(x,  p1, 1280, 1280);
    pyrdown4_kernel<<<nblk((long long)NPLANES * 320 * 80,  T), T>>>(p1, p2, 640, 640);
    pyrdown4_kernel<<<nblk((long long)NPLANES * 160 * 40,  T), T>>>(p2, p3, 320, 320);
    pyrdown4_kernel<<<nblk((long long)NPLANES * 80 * 20,   T), T>>>(p3, p4, 160, 160);
    smallpyr_kernel<<<NPLANES, 256>>>(p4, p5, p6, p7, p8);

    // All three blur+upsample chains (to 160 level) in one launch
    chains_kernel<<<dim3(NPLANES, 3), 256>>>(p5, p7, p8, chA, chB, t160);

    // Packed 160 -> 320 upsample of all three filters
    pack_kernel<<<nblk((long long)NPLANES * 320 * 320, T), T>>>(t160, pack);

    // Final fused composite at 1280x1280 (320->640->1280 inline, quad/thread)
    composite_quad_kernel<<<nblk((long long)8 * 640 * 640, 128), 128>>>(x, pack, out);
}

// round 7
// speedup vs baseline: 3.5134x; 1.9102x over previous
#include <cuda_runtime.h>
#include <math.h>

#define NPLANES 24
#define H0 1280
#define W0 1280

// ---------------------------------------------------------------------------
// Scratch
// ---------------------------------------------------------------------------
__device__ float g_pyr1[NPLANES * 640 * 640];
__device__ float g_pyr2[NPLANES * 320 * 320];
__device__ float g_pyr3[NPLANES * 160 * 160];
__device__ float g_pyr4[NPLANES * 80 * 80];
__device__ float g_pyr5[NPLANES * 40 * 40];
__device__ float g_pyr6[NPLANES * 20 * 20];
__device__ float g_pyr7[NPLANES * 10 * 10];
__device__ float g_pyr8[NPLANES * 5 * 5];

__device__ float g_chA[3 * NPLANES * 40 * 40];
__device__ float g_chB[3 * NPLANES * 40 * 40];
__device__ float g_t80[3 * NPLANES * 80 * 80];     // chain outputs at 80 level
__device__ float4 g_pack[NPLANES * 320 * 320];      // {f30,f150,f300,0} at 320

__device__ __forceinline__ int refl101(int i, int n) {
    if (i < 0) i = -i;
    if (i >= n) i = 2 * n - 2 - i;
    return i;
}

// ---------------------------------------------------------------------------
// pyrDown, 4 outputs/thread, float4 interior loads.
// ---------------------------------------------------------------------------
__global__ void pyrdown4_kernel(const float* __restrict__ src,
                                float* __restrict__ dst, int H, int W) {
    const int Ho = H >> 1, Wo = W >> 1, Wq = Wo >> 2;
    const int total = NPLANES * Ho * Wq;
    int idx = blockIdx.x * blockDim.x + threadIdx.x;
    if (idx >= total) return;
    int wq = idx % Wq;
    int t  = idx / Wq;
    int ho = t % Ho;
    int p  = t / Ho;
    int wo0 = wq << 2;

    const float* s = src + (size_t)p * H * W;
    const float kk[5] = {0.0625f, 0.25f, 0.375f, 0.25f, 0.0625f};
    float acc[4] = {0.f, 0.f, 0.f, 0.f};

    bool interior = (ho >= 1) && (2 * ho + 2 <= H - 1) &&
                    (wq >= 1) && (8 * wq + 11 <= W - 1);
    if (interior) {
        const float* rowp = s + (size_t)(2 * ho - 2) * W + (8 * wq - 4);
#pragma unroll
        for (int dy = 0; dy < 5; dy++, rowp += W) {
            const float4* r4 = (const float4*)rowp;
            float4 A = r4[0], B = r4[1], C = r4[2], D = r4[3];
            float v[16] = {A.x, A.y, A.z, A.w, B.x, B.y, B.z, B.w,
                           C.x, C.y, C.z, C.w, D.x, D.y, D.z, D.w};
            float ky = kk[dy];
#pragma unroll
            for (int o = 0; o < 4; o++) {
                // needed input col rel base = 2o + dx + 2
                float hs = 0.0625f * (v[2 * o + 2] + v[2 * o + 6])
                         + 0.25f   * (v[2 * o + 3] + v[2 * o + 5])
                         + 0.375f  *  v[2 * o + 4];
                acc[o] += ky * hs;
            }
        }
    } else {
#pragma unroll
        for (int o = 0; o < 4; o++) {
            int wo = wo0 + o;
            float a = 0.f;
#pragma unroll
            for (int dy = 0; dy < 5; dy++) {
                int y = refl101(2 * ho + dy - 2, H);
                const float* row = s + (size_t)y * W;
                float r2 = 0.f;
#pragma unroll
                for (int dx = 0; dx < 5; dx++)
                    r2 += kk[dx] * row[refl101(2 * wo + dx - 2, W)];
                a += kk[dy] * r2;
            }
            acc[o] = a;
        }
    }
    float4* d = (float4*)(dst + (size_t)p * Ho * Wo + (size_t)ho * Wo + wo0);
    *d = make_float4(acc[0], acc[1], acc[2], acc[3]);
}

// ---------------------------------------------------------------------------
// Per-plane device helpers
// ---------------------------------------------------------------------------
__device__ void pyrdown_plane(const float* __restrict__ s, float* __restrict__ d,
                              int N, int tid, int nt) {
    const int No = N >> 1;
    const int total = No * No;
    const float kk[5] = {0.0625f, 0.25f, 0.375f, 0.25f, 0.0625f};
    for (int idx = tid; idx < total; idx += nt) {
        int wo = idx % No, ho = idx / No;
        float acc = 0.f;
#pragma unroll
        for (int dy = 0; dy < 5; dy++) {
            int y = refl101(2 * ho + dy - 2, N);
            const float* row = s + y * N;
            float r = 0.f;
#pragma unroll
            for (int dx = 0; dx < 5; dx++)
                r += kk[dx] * row[refl101(2 * wo + dx - 2, N)];
            acc += kk[dy] * r;
        }
        d[idx] = acc;
    }
}

__device__ void up2_plane(const float* __restrict__ s, float* __restrict__ d,
                          int N, int tid, int nt) {
    const int No = 2 * N;
    const int total = No * No;
    for (int idx = tid; idx < total; idx += nt) {
        int wo = idx % No, ho = idx / No;
        int iy = (ho >> 1) + (ho & 1) - 1;
        float fy = (ho & 1) ? 0.25f : 0.75f;
        int y0 = max(iy, 0), y1 = min(iy + 1, N - 1);
        int ix = (wo >> 1) + (wo & 1) - 1;
        float fx = (wo & 1) ? 0.25f : 0.75f;
        int x0 = max(ix, 0), x1 = min(ix + 1, N - 1);
        float v00 = s[y0 * N + x0], v01 = s[y0 * N + x1];
        float v10 = s[y1 * N + x0], v11 = s[y1 * N + x1];
        float tp = v00 + fx * (v01 - v00);
        float bt = v10 + fx * (v11 - v10);
        d[idx] = tp + fy * (bt - tp);
    }
}

__device__ void blur_plane(const float* __restrict__ s, float* __restrict__ d,
                           int N, int ks, int tid, int nt) {
    float g[9];
    float sg = 0.3f * ((ks - 1) * 0.5f - 1.f) + 0.8f;
    float inv2s2 = 1.f / (2.f * sg * sg);
    float sum = 0.f;
    for (int i = 0; i < ks; i++) {
        float dd = (float)i - (ks - 1) * 0.5f;
        g[i] = expf(-dd * dd * inv2s2);
        sum += g[i];
    }
    float inv = 1.f / sum;
    for (int i = 0; i < ks; i++) g[i] *= inv;

    int P = ks / 2;
    const int total = N * N;
    for (int idx = tid; idx < total; idx += nt) {
        int w = idx % N, h = idx / N;
        float acc = 0.f;
        for (int dy = 0; dy < ks; dy++) {
            int y = refl101(h + dy - P, N);
            const float* row = s + y * N;
            float r = 0.f;
            for (int dx = 0; dx < ks; dx++)
                r += g[dx] * row[refl101(w + dx - P, N)];
            acc += g[dy] * r;
        }
        d[idx] = acc;
    }
}

// ---------------------------------------------------------------------------
// Fused small pyramid: 320 -> 160 -> 80 -> 40 -> 20 -> 10 -> 5, block/plane.
// ---------------------------------------------------------------------------
__global__ void smallpyr_kernel(const float* __restrict__ p2,
                                float* __restrict__ p3, float* __restrict__ p4,
                                float* __restrict__ p5, float* __restrict__ p6,
                                float* __restrict__ p7, float* __restrict__ p8) {
    int p = blockIdx.x;
    int tid = threadIdx.x, nt = blockDim.x;
    pyrdown_plane(p2 + (size_t)p * 102400, p3 + (size_t)p * 25600, 320, tid, nt);
    __syncthreads();
    pyrdown_plane(p3 + (size_t)p * 25600, p4 + (size_t)p * 6400, 160, tid, nt);
    __syncthreads();
    pyrdown_plane(p4 + (size_t)p * 6400, p5 + (size_t)p * 1600, 80, tid, nt);
    __syncthreads();
    pyrdown_plane(p5 + (size_t)p * 1600, p6 + (size_t)p * 400, 40, tid, nt);
    __syncthreads();
    pyrdown_plane(p6 + (size_t)p * 400, p7 + (size_t)p * 100, 20, tid, nt);
    __syncthreads();
    pyrdown_plane(p7 + (size_t)p * 100, p8 + (size_t)p * 25, 10, tid, nt);
}

// ---------------------------------------------------------------------------
// Fused chains: block = (plane, sigma). blur + up2 chain to 80 level.
// ---------------------------------------------------------------------------
__global__ void chains_kernel(const float* __restrict__ p5,
                              const float* __restrict__ p7,
                              const float* __restrict__ p8,
                              float* __restrict__ chA, float* __restrict__ chB,
                              float* __restrict__ t80) {
    int p = blockIdx.x;
    int sg = blockIdx.y;
    int tid = threadIdx.x, nt = blockDim.x;
    size_t so = (size_t)sg * NPLANES + p;
    float* A = chA + so * 1600;
    float* B = chB + so * 1600;
    float* T = t80 + so * 6400;

    if (sg == 0) {
        blur_plane(p5 + (size_t)p * 1600, A, 40, 7, tid, nt); __syncthreads();
        up2_plane(A, T, 40, tid, nt);
    } else if (sg == 1) {
        blur_plane(p7 + (size_t)p * 100, A, 10, 9, tid, nt); __syncthreads();
        up2_plane(A, B, 10, tid, nt); __syncthreads();
        up2_plane(B, A, 20, tid, nt); __syncthreads();
        up2_plane(A, T, 40, tid, nt);
    } else {
        blur_plane(p8 + (size_t)p * 25, A, 5, 9, tid, nt); __syncthreads();
        up2_plane(A, B, 5, tid, nt); __syncthreads();
        up2_plane(B, A, 10, tid, nt); __syncthreads();
        up2_plane(A, B, 20, tid, nt); __syncthreads();
        up2_plane(B, T, 40, tid, nt);
    }
}

// ---------------------------------------------------------------------------
// Polyphase double-up (two chained 2x bilinear upsamples) 4-phase weights.
// Output row 4m+ph draws on source rows {m-1, m, m+1} (clamped).
// Exactly reproduces chained up2 (incl. borders via index clamping).
// ---------------------------------------------------------------------------
__device__ __constant__ float W4[4][3] = {
    {0.375f,  0.625f, 0.f},
    {0.1875f, 0.75f,  0.0625f},
    {0.0625f, 0.75f,  0.1875f},
    {0.f,     0.625f, 0.375f}
};

// ---------------------------------------------------------------------------
// pack80: 80 -> 320 double-up of the three filters, packed float4 output.
// One thread per 80-cell per plane -> 4x4 outputs from a 3x3 patch.
// ---------------------------------------------------------------------------
__global__ void __launch_bounds__(128)
pack80_kernel(const float* __restrict__ t80, float4* __restrict__ pack) {
    const int total = NPLANES * 80 * 80;
    int idx = blockIdx.x * blockDim.x + threadIdx.x;
    if (idx >= total) return;
    int q = idx % 80;
    int t = idx / 80;
    int m = t % 80;
    int p = t / 80;

    int pr[3] = {max(m - 1, 0), m, min(m + 1, 79)};
    int pc[3] = {max(q - 1, 0), q, min(q + 1, 79)};

    float P[3][3][3];   // [sigma][row][col]
#pragma unroll
    for (int s = 0; s < 3; s++) {
        const float* f = t80 + ((size_t)s * NPLANES + p) * 6400;
#pragma unroll
        for (int a = 0; a < 3; a++)
#pragma unroll
            for (int b = 0; b < 3; b++)
                P[s][a][b] = f[pr[a] * 80 + pc[b]];
    }

    float4* op = pack + (size_t)p * 320 * 320;
#pragma unroll
    for (int py = 0; py < 4; py++) {
        float R[3][3];  // [sigma][col]
#pragma unroll
        for (int s = 0; s < 3; s++)
#pragma unroll
            for (int b = 0; b < 3; b++)
                R[s][b] = W4[py][0] * P[s][0][b] + W4[py][1] * P[s][1][b]
                        + W4[py][2] * P[s][2][b];
        float4* orow = op + (size_t)(4 * m + py) * 320 + 4 * q;
#pragma unroll
        for (int px = 0; px < 4; px++) {
            float w0 = W4[px][0], w1 = W4[px][1], w2 = W4[px][2];
            float4 v;
            v.x = w0 * R[0][0] + w1 * R[0][1] + w2 * R[0][2];
            v.y = w0 * R[1][0] + w1 * R[1][1] + w2 * R[1][2];
            v.z = w0 * R[2][0] + w1 * R[2][1] + w2 * R[2][2];
            v.w = 0.f;
            orow[px] = v;
        }
    }
}

// ---------------------------------------------------------------------------
// Composite: one thread per 320-cell -> 4x4 output pixels, 3 channels.
// Double-up 320->1280 via polyphase 3x3 patch, then retinex + color restore.
// ---------------------------------------------------------------------------
__global__ void __launch_bounds__(128)
composite_kernel(const float* __restrict__ x,
                 const float4* __restrict__ pack,
                 float* __restrict__ out) {
    const int total = 8 * 320 * 320;
    int idx = blockIdx.x * blockDim.x + threadIdx.x;
    if (idx >= total) return;
    int q = idx % 320;
    int t = idx / 320;
    int m = t % 320;
    int n = t / 320;

    int pr[3] = {max(m - 1, 0), m, min(m + 1, 319)};
    int pc[3] = {max(q - 1, 0), q, min(q + 1, 319)};

    const float EPS = 1e-6f;
    const float LOG10_2 = 0.30102999566398f;

    float lp[3][16];

#pragma unroll
    for (int c = 0; c < 3; c++) {
        const float4* pp = pack + (size_t)(n * 3 + c) * 320 * 320;
        float4 P[3][3];
#pragma unroll
        for (int a = 0; a < 3; a++)
#pragma unroll
            for (int b = 0; b < 3; b++)
                P[a][b] = pp[(size_t)pr[a] * 320 + pc[b]];

#pragma unroll
        for (int py = 0; py < 4; py++) {
            float w0 = W4[py][0], w1 = W4[py][1], w2 = W4[py][2];
            float4 R[3];
#pragma unroll
            for (int b = 0; b < 3; b++) {
                R[b].x = w0 * P[0][b].x + w1 * P[1][b].x + w2 * P[2][b].x;
                R[b].y = w0 * P[0][b].y + w1 * P[1][b].y + w2 * P[2][b].y;
                R[b].z = w0 * P[0][b].z + w1 * P[1][b].z + w2 * P[2][b].z;
            }
#pragma unroll
            for (int px = 0; px < 4; px++) {
                float u0 = W4[px][0], u1 = W4[px][1], u2 = W4[px][2];
                float vx = u0 * R[0].x + u1 * R[1].x + u2 * R[2].x;
                float vy = u0 * R[0].y + u1 * R[1].y + u2 * R[2].y;
                float vz = u0 * R[0].z + u1 * R[1].z + u2 * R[2].z;
                float a  = 255.f * vx + 1.f;
                float b  = 255.f * vy + 1.f;
                float cc = 255.f * vz + 1.f;
                lp[c][py * 4 + px] = __log2f((a + EPS) * (b + EPS) * (cc + EPS));
            }
        }
    }

#pragma unroll
    for (int py = 0; py < 4; py++) {
        float4 xr[3];
#pragma unroll
        for (int c = 0; c < 3; c++)
            xr[c] = *(const float4*)(x + (size_t)(n * 3 + c) * H0 * W0
                                       + (size_t)(4 * m + py) * W0 + 4 * q);
        float4 o[3];
#pragma unroll
        for (int px = 0; px < 4; px++) {
            float im0 = ((const float*)&xr[0])[px] * 255.f + 1.f;
            float im1 = ((const float*)&xr[1])[px] * 255.f + 1.f;
            float im2 = ((const float*)&xr[2])[px] * 255.f + 1.f;
            float inv_sum = 2.f / (im0 + im1 + im2 + EPS);
            float im[3] = {im0, im1, im2};
#pragma unroll
            for (int c = 0; c < 3; c++) {
                float retinex = (__log2f(im[c] + EPS)
                               - lp[c][py * 4 + px] * (1.f / 3.f)) * LOG10_2;
                float cr = __log2f(im[c] * inv_sum + 1.f) * LOG10_2;
                float e = retinex * cr * 2700.f + 128.f;
                e = fminf(fmaxf(e, 0.f), 255.f);
                ((float*)&o[c])[px] = e * (1.f / 255.f);
            }
        }
#pragma unroll
        for (int c = 0; c < 3; c++)
            *(float4*)(out + (size_t)(n * 3 + c) * H0 * W0
                           + (size_t)(4 * m + py) * W0 + 4 * q) = o[c];
    }
}

// ---------------------------------------------------------------------------
// Launch
// ---------------------------------------------------------------------------
static inline int nblk(long long n, int t) { return (int)((n + t - 1) / t); }

extern "C" void kernel_launch(void* const* d_in, const int* in_sizes, int n_in,
                              void* d_out, int out_size) {
    const float* x = (const float*)d_in[0];
    float* out = (float*)d_out;

    float *p1, *p2, *p3, *p4, *p5, *p6, *p7, *p8;
    float *chA, *chB, *t80;
    float4* pack;
    cudaGetSymbolAddress((void**)&p1, g_pyr1);
    cudaGetSymbolAddress((void**)&p2, g_pyr2);
    cudaGetSymbolAddress((void**)&p3, g_pyr3);
    cudaGetSymbolAddress((void**)&p4, g_pyr4);
    cudaGetSymbolAddress((void**)&p5, g_pyr5);
    cudaGetSymbolAddress((void**)&p6, g_pyr6);
    cudaGetSymbolAddress((void**)&p7, g_pyr7);
    cudaGetSymbolAddress((void**)&p8, g_pyr8);
    cudaGetSymbolAddress((void**)&chA, g_chA);
    cudaGetSymbolAddress((void**)&chB, g_chB);
    cudaGetSymbolAddress((void**)&t80, g_t80);
    cudaGetSymbolAddress((void**)&pack, g_pack);

    const int T = 256;
    pyrdown4_kernel<<<nblk((long long)NPLANES * 640 * 160, T), T>>>(x,  p1, 1280, 1280);
    pyrdown4_kernel<<<nblk((long long)NPLANES * 320 * 80,  T), T>>>(p1, p2, 640, 640);
    smallpyr_kernel<<<NPLANES, 512>>>(p2, p3, p4, p5, p6, p7, p8);
    chains_kernel<<<dim3(NPLANES, 3), 256>>>(p5, p7, p8, chA, chB, t80);
    pack80_kernel<<<nblk((long long)NPLANES * 80 * 80, 128), 128>>>(t80, pack);
    composite_kernel<<<nblk((long long)8 * 320 * 320, 128), 128>>>(x, pack, out);
}

// round 8
// speedup vs baseline: 4.4142x; 1.2564x over previous
#include <cuda_runtime.h>
#include <math.h>

#define NPLANES 24
#define H0 1280
#define W0 1280

// ---------------------------------------------------------------------------
// Scratch
// ---------------------------------------------------------------------------
__device__ float g_pyr1[NPLANES * 640 * 640];
__device__ float g_pyr2[NPLANES * 320 * 320];
__device__ float g_pyr3[NPLANES * 160 * 160];
__device__ float g_pyr4[NPLANES * 80 * 80];
__device__ float g_t80[3 * NPLANES * 80 * 80];     // chain outputs at 80 level
__device__ float4 g_pack[NPLANES * 320 * 320];      // {f30,f150,f300,0} at 320

__device__ __forceinline__ int refl101(int i, int n) {
    if (i < 0) i = -i;
    if (i >= n) i = 2 * n - 2 - i;
    return i;
}

// ---------------------------------------------------------------------------
// f32x2 packed helpers (Blackwell): two fp32 lanes per 64-bit reg.
// ---------------------------------------------------------------------------
typedef unsigned long long ull;
__device__ __forceinline__ ull pk2(float a, float b) {
    ull r;
    asm("mov.b64 %0, {%1, %2};" : "=l"(r)
        : "r"(__float_as_uint(a)), "r"(__float_as_uint(b)));
    return r;
}
__device__ __forceinline__ void upk2(ull v, float& a, float& b) {
    unsigned int lo, hi;
    asm("mov.b64 {%0, %1}, %2;" : "=r"(lo), "=r"(hi) : "l"(v));
    a = __uint_as_float(lo);
    b = __uint_as_float(hi);
}
__device__ __forceinline__ ull fma2(ull a, ull b, ull c) {
    ull r;
    asm("fma.rn.f32x2 %0, %1, %2, %3;" : "=l"(r) : "l"(a), "l"(b), "l"(c));
    return r;
}
__device__ __forceinline__ ull mul2(ull a, ull b) {
    ull r;
    asm("mul.rn.f32x2 %0, %1, %2;" : "=l"(r) : "l"(a), "l"(b));
    return r;
}

// ---------------------------------------------------------------------------
// pyrDown, 4 outputs/thread, float4 interior loads.
// ---------------------------------------------------------------------------
__global__ void pyrdown4_kernel(const float* __restrict__ src,
                                float* __restrict__ dst, int H, int W) {
    const int Ho = H >> 1, Wo = W >> 1, Wq = Wo >> 2;
    const int total = NPLANES * Ho * Wq;
    int idx = blockIdx.x * blockDim.x + threadIdx.x;
    if (idx >= total) return;
    int wq = idx % Wq;
    int t  = idx / Wq;
    int ho = t % Ho;
    int p  = t / Ho;
    int wo0 = wq << 2;

    const float* s = src + (size_t)p * H * W;
    const float kk[5] = {0.0625f, 0.25f, 0.375f, 0.25f, 0.0625f};
    float acc[4] = {0.f, 0.f, 0.f, 0.f};

    bool interior = (ho >= 1) && (2 * ho + 2 <= H - 1) &&
                    (wq >= 1) && (8 * wq + 11 <= W - 1);
    if (interior) {
        const float* rowp = s + (size_t)(2 * ho - 2) * W + (8 * wq - 4);
#pragma unroll
        for (int dy = 0; dy < 5; dy++, rowp += W) {
            const float4* r4 = (const float4*)rowp;
            float4 A = r4[0], B = r4[1], C = r4[2], D = r4[3];
            float v[16] = {A.x, A.y, A.z, A.w, B.x, B.y, B.z, B.w,
                           C.x, C.y, C.z, C.w, D.x, D.y, D.z, D.w};
            float ky = kk[dy];
#pragma unroll
            for (int o = 0; o < 4; o++) {
                float hs = 0.0625f * (v[2 * o + 2] + v[2 * o + 6])
                         + 0.25f   * (v[2 * o + 3] + v[2 * o + 5])
                         + 0.375f  *  v[2 * o + 4];
                acc[o] += ky * hs;
            }
        }
    } else {
#pragma unroll
        for (int o = 0; o < 4; o++) {
            int wo = wo0 + o;
            float a = 0.f;
#pragma unroll
            for (int dy = 0; dy < 5; dy++) {
                int y = refl101(2 * ho + dy - 2, H);
                const float* row = s + (size_t)y * W;
                float r2 = 0.f;
#pragma unroll
                for (int dx = 0; dx < 5; dx++)
                    r2 += kk[dx] * row[refl101(2 * wo + dx - 2, W)];
                a += kk[dy] * r2;
            }
            acc[o] = a;
        }
    }
    float4* d = (float4*)(dst + (size_t)p * Ho * Wo + (size_t)ho * Wo + wo0);
    *d = make_float4(acc[0], acc[1], acc[2], acc[3]);
}

// ---------------------------------------------------------------------------
// Generic-pointer per-plane helpers (work on smem or gmem)
// ---------------------------------------------------------------------------
__device__ void pyrdown_plane(const float* s, float* d, int N, int tid, int nt) {
    const int No = N >> 1;
    const int total = No * No;
    const float kk[5] = {0.0625f, 0.25f, 0.375f, 0.25f, 0.0625f};
    for (int idx = tid; idx < total; idx += nt) {
        int wo = idx % No, ho = idx / No;
        float acc = 0.f;
#pragma unroll
        for (int dy = 0; dy < 5; dy++) {
            int y = refl101(2 * ho + dy - 2, N);
            const float* row = s + y * N;
            float r = 0.f;
#pragma unroll
            for (int dx = 0; dx < 5; dx++)
                r += kk[dx] * row[refl101(2 * wo + dx - 2, N)];
            acc += kk[dy] * r;
        }
        d[idx] = acc;
    }
}

__device__ void up2_plane(const float* s, float* d, int N, int tid, int nt) {
    const int No = 2 * N;
    const int total = No * No;
    for (int idx = tid; idx < total; idx += nt) {
        int wo = idx % No, ho = idx / No;
        int iy = (ho >> 1) + (ho & 1) - 1;
        float fy = (ho & 1) ? 0.25f : 0.75f;
        int y0 = max(iy, 0), y1 = min(iy + 1, N - 1);
        int ix = (wo >> 1) + (wo & 1) - 1;
        float fx = (wo & 1) ? 0.25f : 0.75f;
        int x0 = max(ix, 0), x1 = min(ix + 1, N - 1);
        float v00 = s[y0 * N + x0], v01 = s[y0 * N + x1];
        float v10 = s[y1 * N + x0], v11 = s[y1 * N + x1];
        float tp = v00 + fx * (v01 - v00);
        float bt = v10 + fx * (v11 - v10);
        d[idx] = tp + fy * (bt - tp);
    }
}

__device__ void blur_plane(const float* s, float* d, int N, int ks,
                           int tid, int nt) {
    float g[9];
    float sg = 0.3f * ((ks - 1) * 0.5f - 1.f) + 0.8f;
    float inv2s2 = 1.f / (2.f * sg * sg);
    float sum = 0.f;
    for (int i = 0; i < ks; i++) {
        float dd = (float)i - (ks - 1) * 0.5f;
        g[i] = expf(-dd * dd * inv2s2);
        sum += g[i];
    }
    float inv = 1.f / sum;
    for (int i = 0; i < ks; i++) g[i] *= inv;

    int P = ks / 2;
    const int total = N * N;
    for (int idx = tid; idx < total; idx += nt) {
        int w = idx % N, h = idx / N;
        float acc = 0.f;
        for (int dy = 0; dy < ks; dy++) {
            int y = refl101(h + dy - P, N);
            const float* row = s + y * N;
            float r = 0.f;
            for (int dx = 0; dx < ks; dx++)
                r += g[dx] * row[refl101(w + dx - P, N)];
            acc += g[dy] * r;
        }
        d[idx] = acc;
    }
}

// ---------------------------------------------------------------------------
// prep: block = (plane, sigma). Loads the 80-level plane into smem, builds its
// own small pyramid in smem, blurs, runs the up-chain in smem, writes only the
// 80-level filter result to global. All intermediates stay in shared memory.
// ---------------------------------------------------------------------------
__global__ void __launch_bounds__(256)
prep_kernel(const float* __restrict__ p4, float* __restrict__ t80) {
    __shared__ float s80[6400];
    __shared__ float s40[1600];
    __shared__ float s20[400];
    __shared__ float s10[100];
    __shared__ float s5[25];
    __shared__ float A[1600];
    __shared__ float B[1600];

    int p = blockIdx.x;
    int sg = blockIdx.y;
    int tid = threadIdx.x, nt = blockDim.x;

    // load 80x80 plane (float4)
    const float4* src4 = (const float4*)(p4 + (size_t)p * 6400);
    for (int i = tid; i < 1600; i += nt)
        ((float4*)s80)[i] = src4[i];
    __syncthreads();

    pyrdown_plane(s80, s40, 80, tid, nt);
    __syncthreads();
    if (sg >= 1) {
        pyrdown_plane(s40, s20, 40, tid, nt);
        __syncthreads();
        pyrdown_plane(s20, s10, 20, tid, nt);
        __syncthreads();
    }
    if (sg == 2) {
        pyrdown_plane(s10, s5, 10, tid, nt);
        __syncthreads();
    }

    float* T = t80 + ((size_t)sg * NPLANES + p) * 6400;

    if (sg == 0) {
        blur_plane(s40, A, 40, 7, tid, nt); __syncthreads();
        up2_plane(A, T, 40, tid, nt);
    } else if (sg == 1) {
        blur_plane(s10, A, 10, 9, tid, nt); __syncthreads();
        up2_plane(A, B, 10, tid, nt); __syncthreads();
        up2_plane(B, A, 20, tid, nt); __syncthreads();
        up2_plane(A, T, 40, tid, nt);
    } else {
        blur_plane(s5, A, 5, 9, tid, nt); __syncthreads();
        up2_plane(A, B, 5, tid, nt); __syncthreads();
        up2_plane(B, A, 10, tid, nt); __syncthreads();
        up2_plane(A, B, 20, tid, nt); __syncthreads();
        up2_plane(B, T, 40, tid, nt);
    }
}

// ---------------------------------------------------------------------------
// Polyphase double-up weights: output row 4m+ph draws source rows {m-1,m,m+1}.
// ---------------------------------------------------------------------------
__device__ __constant__ float W4[4][3] = {
    {0.375f,  0.625f, 0.f},
    {0.1875f, 0.75f,  0.0625f},
    {0.0625f, 0.75f,  0.1875f},
    {0.f,     0.625f, 0.375f}
};

// ---------------------------------------------------------------------------
// pack80: 80 -> 320 double-up of the three filters -> packed float4.
// ---------------------------------------------------------------------------
__global__ void __launch_bounds__(128)
pack80_kernel(const float* __restrict__ t80, float4* __restrict__ pack) {
    const int total = NPLANES * 80 * 80;
    int idx = blockIdx.x * blockDim.x + threadIdx.x;
    if (idx >= total) return;
    int q = idx % 80;
    int t = idx / 80;
    int m = t % 80;
    int p = t / 80;

    int pr[3] = {max(m - 1, 0), m, min(m + 1, 79)};
    int pc[3] = {max(q - 1, 0), q, min(q + 1, 79)};

    float P[3][3][3];   // [sigma][row][col]
#pragma unroll
    for (int s = 0; s < 3; s++) {
        const float* f = t80 + ((size_t)s * NPLANES + p) * 6400;
#pragma unroll
        for (int a = 0; a < 3; a++)
#pragma unroll
            for (int b = 0; b < 3; b++)
                P[s][a][b] = f[pr[a] * 80 + pc[b]];
    }

    float4* op = pack + (size_t)p * 320 * 320;
#pragma unroll
    for (int py = 0; py < 4; py++) {
        float R[3][3];
#pragma unroll
        for (int s = 0; s < 3; s++)
#pragma unroll
            for (int b = 0; b < 3; b++)
                R[s][b] = W4[py][0] * P[s][0][b] + W4[py][1] * P[s][1][b]
                        + W4[py][2] * P[s][2][b];
        float4* orow = op + (size_t)(4 * m + py) * 320 + 4 * q;
#pragma unroll
        for (int px = 0; px < 4; px++) {
            float w0 = W4[px][0], w1 = W4[px][1], w2 = W4[px][2];
            float4 v;
            v.x = w0 * R[0][0] + w1 * R[0][1] + w2 * R[0][2];
            v.y = w0 * R[1][0] + w1 * R[1][1] + w2 * R[1][2];
            v.z = w0 * R[2][0] + w1 * R[2][1] + w2 * R[2][2];
            v.w = 0.f;
            orow[px] = v;
        }
    }
}

// ---------------------------------------------------------------------------
// Composite: one thread per 320-cell -> 4x4 output pixels, 3 channels.
// Polyphase 320->1280; (f30,f150) lanes computed with packed f32x2 FMA.
// ---------------------------------------------------------------------------
__global__ void __launch_bounds__(128)
composite_kernel(const float* __restrict__ x,
                 const float4* __restrict__ pack,
                 float* __restrict__ out) {
    const int total = 8 * 320 * 320;
    int idx = blockIdx.x * blockDim.x + threadIdx.x;
    if (idx >= total) return;
    int q = idx % 320;
    int t = idx / 320;
    int m = t % 320;
    int n = t / 320;

    int pr[3] = {max(m - 1, 0), m, min(m + 1, 319)};
    int pc[3] = {max(q - 1, 0), q, min(q + 1, 319)};

    const float EPS = 1e-6f;
    const float LOG10_2 = 0.30102999566398f;

    // packed per-phase weights
    ull w2p[4][3];
#pragma unroll
    for (int ph = 0; ph < 4; ph++)
#pragma unroll
        for (int k = 0; k < 3; k++)
            w2p[ph][k] = pk2(W4[ph][k], W4[ph][k]);

    float lp[3][16];

#pragma unroll
    for (int c = 0; c < 3; c++) {
        const float4* pp = pack + (size_t)(n * 3 + c) * 320 * 320;
        ull Pab[3][3];    // packed (f30, f150)
        float Pz[3][3];   // f300
#pragma unroll
        for (int a = 0; a < 3; a++)
#pragma unroll
            for (int b = 0; b < 3; b++) {
                float4 v = pp[(size_t)pr[a] * 320 + pc[b]];
                Pab[a][b] = pk2(v.x, v.y);
                Pz[a][b]  = v.z;
            }

#pragma unroll
        for (int py = 0; py < 4; py++) {
            float w0 = W4[py][0], w1 = W4[py][1], w2 = W4[py][2];
            ull Rab[3];
            float Rz[3];
#pragma unroll
            for (int b = 0; b < 3; b++) {
                Rab[b] = fma2(Pab[2][b], w2p[py][2],
                         fma2(Pab[1][b], w2p[py][1],
                         mul2(Pab[0][b], w2p[py][0])));
                Rz[b] = w0 * Pz[0][b] + w1 * Pz[1][b] + w2 * Pz[2][b];
            }
#pragma unroll
            for (int px = 0; px < 4; px++) {
                ull vab = fma2(Rab[2], w2p[px][2],
                          fma2(Rab[1], w2p[px][1],
                          mul2(Rab[0], w2p[px][0])));
                float u0 = W4[px][0], u1 = W4[px][1], u2 = W4[px][2];
                float vz = u0 * Rz[0] + u1 * Rz[1] + u2 * Rz[2];
                float vx, vy;
                upk2(vab, vx, vy);
                float a  = 255.f * vx + 1.f;
                float b  = 255.f * vy + 1.f;
                float cc = 255.f * vz + 1.f;
                lp[c][py * 4 + px] = __log2f((a + EPS) * (b + EPS) * (cc + EPS));
            }
        }
    }

#pragma unroll
    for (int py = 0; py < 4; py++) {
        float4 xr[3];
#pragma unroll
        for (int c = 0; c < 3; c++)
            xr[c] = *(const float4*)(x + (size_t)(n * 3 + c) * H0 * W0
                                       + (size_t)(4 * m + py) * W0 + 4 * q);
        float4 o[3];
#pragma unroll
        for (int px = 0; px < 4; px++) {
            float im0 = ((const float*)&xr[0])[px] * 255.f + 1.f;
            float im1 = ((const float*)&xr[1])[px] * 255.f + 1.f;
            float im2 = ((const float*)&xr[2])[px] * 255.f + 1.f;
            float inv_sum = 2.f / (im0 + im1 + im2 + EPS);
            float im[3] = {im0, im1, im2};
#pragma unroll
            for (int c = 0; c < 3; c++) {
                float retinex = (__log2f(im[c] + EPS)
                               - lp[c][py * 4 + px] * (1.f / 3.f)) * LOG10_2;
                float cr = __log2f(im[c] * inv_sum + 1.f) * LOG10_2;
                float e = retinex * cr * 2700.f + 128.f;
                e = fminf(fmaxf(e, 0.f), 255.f);
                ((float*)&o[c])[px] = e * (1.f / 255.f);
            }
        }
#pragma unroll
        for (int c = 0; c < 3; c++)
            *(float4*)(out + (size_t)(n * 3 + c) * H0 * W0
                           + (size_t)(4 * m + py) * W0 + 4 * q) = o[c];
    }
}

// ---------------------------------------------------------------------------
// Launch
// ---------------------------------------------------------------------------
static inline int nblk(long long n, int t) { return (int)((n + t - 1) / t); }

extern "C" void kernel_launch(void* const* d_in, const int* in_sizes, int n_in,
                              void* d_out, int out_size) {
    const float* x = (const float*)d_in[0];
    float* out = (float*)d_out;

    float *p1, *p2, *p3, *p4, *t80;
    float4* pack;
    cudaGetSymbolAddress((void**)&p1, g_pyr1);
    cudaGetSymbolAddress((void**)&p2, g_pyr2);
    cudaGetSymbolAddress((void**)&p3, g_pyr3);
    cudaGetSymbolAddress((void**)&p4, g_pyr4);
    cudaGetSymbolAddress((void**)&t80, g_t80);
    cudaGetSymbolAddress((void**)&pack, g_pack);

    const int T = 256;
    pyrdown4_kernel<<<nblk((long long)NPLANES * 640 * 160, T), T>>>(x,  p1, 1280, 1280);
    pyrdown4_kernel<<<nblk((long long)NPLANES * 320 * 80,  T), T>>>(p1, p2, 640, 640);
    pyrdown4_kernel<<<nblk((long long)NPLANES * 160 * 40,  T), T>>>(p2, p3, 320, 320);
    pyrdown4_kernel<<<nblk((long long)NPLANES * 80 * 20,   T), T>>>(p3, p4, 160, 160);
    prep_kernel<<<dim3(NPLANES, 3), 256>>>(p4, t80);
    pack80_kernel<<<nblk((long long)NPLANES * 80 * 80, 128), 128>>>(t80, pack);
    composite_kernel<<<nblk((long long)8 * 320 * 320, 128), 128>>>(x, pack, out);
}